// round 12
// baseline (speedup 1.0000x reference)
#include <cuda_runtime.h>
#include <cuda_bf16.h>
#include <cstdint>
#include <math.h>

// Problem constants
#define N_TOKENS 2048
#define F_DIM    2048
#define H_DIM    4096
#define N_EXP    8
#define SEG      2048

// ---------------- device scratch (static globals) ---------------------------
__device__ int   g_topk_idx[N_TOKENS * 2];
__device__ float g_topk_w[N_TOKENS * 2];
__device__ int   g_pair_token[N_EXP * SEG];
__device__ float g_pair_w[N_EXP * SEG];
__device__ int   g_count[N_EXP];

// bf16 hi/lo planes
__device__ __align__(16) __nv_bfloat16 g_Xh[(size_t)N_TOKENS * F_DIM];
__device__ __align__(16) __nv_bfloat16 g_Xl[(size_t)N_TOKENS * F_DIM];
__device__ __align__(16) __nv_bfloat16 g_W1h[(size_t)N_EXP * F_DIM * H_DIM];
__device__ __align__(16) __nv_bfloat16 g_W1l[(size_t)N_EXP * F_DIM * H_DIM];
__device__ __align__(16) __nv_bfloat16 g_W2h[(size_t)N_EXP * H_DIM * F_DIM];
__device__ __align__(16) __nv_bfloat16 g_W2l[(size_t)N_EXP * H_DIM * F_DIM];
__device__ __align__(16) __nv_bfloat16 g_W3h[(size_t)N_EXP * F_DIM * H_DIM];
__device__ __align__(16) __nv_bfloat16 g_W3l[(size_t)N_EXP * F_DIM * H_DIM];
__device__ __align__(16) __nv_bfloat16 g_Hh[(size_t)N_EXP * SEG * H_DIM];
__device__ __align__(16) __nv_bfloat16 g_Hl[(size_t)N_EXP * SEG * H_DIM];

// ---------------- PTX helpers ------------------------------------------------
__device__ __forceinline__ uint32_t smem_u32(const void* p) {
    uint32_t a;
    asm("{ .reg .u64 t; cvta.to.shared.u64 t, %1; cvt.u32.u64 %0, t; }" : "=r"(a) : "l"(p));
    return a;
}

#define CP16(dst, src) \
    asm volatile("cp.async.cg.shared.global [%0], [%1], 16;" \
                 :: "r"(dst), "l"(src) : "memory")
#define CP_COMMIT() asm volatile("cp.async.commit_group;" ::: "memory")
#define CP_WAIT0()  asm volatile("cp.async.wait_group 0;" ::: "memory")
#define CP_WAIT1()  asm volatile("cp.async.wait_group 1;" ::: "memory")

__device__ __forceinline__ void ldsm_x4(uint32_t addr, uint32_t* r) {
    asm volatile("ldmatrix.sync.aligned.m8n8.x4.shared.b16 {%0,%1,%2,%3}, [%4];"
                 : "=r"(r[0]), "=r"(r[1]), "=r"(r[2]), "=r"(r[3]) : "r"(addr));
}
__device__ __forceinline__ void ldsm_x4_t(uint32_t addr, uint32_t* r) {
    asm volatile("ldmatrix.sync.aligned.m8n8.x4.trans.shared.b16 {%0,%1,%2,%3}, [%4];"
                 : "=r"(r[0]), "=r"(r[1]), "=r"(r[2]), "=r"(r[3]) : "r"(addr));
}
__device__ __forceinline__ void mma_bf16(float* d, const uint32_t* a, const uint32_t* b) {
    asm volatile(
        "mma.sync.aligned.m16n8k16.row.col.f32.bf16.bf16.f32 "
        "{%0,%1,%2,%3}, {%4,%5,%6,%7}, {%8,%9}, {%0,%1,%2,%3};"
        : "+f"(d[0]), "+f"(d[1]), "+f"(d[2]), "+f"(d[3])
        : "r"(a[0]), "r"(a[1]), "r"(a[2]), "r"(a[3]), "r"(b[0]), "r"(b[1]));
}

__device__ __forceinline__ void split_pair(float y0, float y1, uint32_t& hi, uint32_t& lo) {
    uint32_t u0 = __float_as_uint(y0), u1 = __float_as_uint(y1);
    hi = __byte_perm(u0, u1, 0x7632);
    float l0 = y0 - __uint_as_float(u0 & 0xffff0000u);
    float l1 = y1 - __uint_as_float(u1 & 0xffff0000u);
    lo = __byte_perm(__float_as_uint(l0), __float_as_uint(l1), 0x7632);
}

// ---------------- preprocessing ----------------------------------------------
// weights: grid.y selects tensor (0=w1,1=w2,2=w3)
__global__ void prep_w_kernel(const float4* __restrict__ w1,
                              const float4* __restrict__ w2,
                              const float4* __restrict__ w3) {
    const size_t n4 = (size_t)N_EXP * F_DIM * H_DIM / 4;
    const float4* src;
    uint2 *hp, *lp;
    if (blockIdx.y == 0)      { src = w1; hp = (uint2*)g_W1h; lp = (uint2*)g_W1l; }
    else if (blockIdx.y == 1) { src = w2; hp = (uint2*)g_W2h; lp = (uint2*)g_W2l; }
    else                      { src = w3; hp = (uint2*)g_W3h; lp = (uint2*)g_W3l; }
    for (size_t i = (size_t)blockIdx.x * blockDim.x + threadIdx.x; i < n4;
         i += (size_t)gridDim.x * blockDim.x) {
        float4 v = src[i];
        uint32_t h01, l01, h23, l23;
        split_pair(v.x, v.y, h01, l01);
        split_pair(v.z, v.w, h23, l23);
        hp[i] = make_uint2(h01, h23);
        lp[i] = make_uint2(l01, l23);
    }
}

__global__ void prep_x_kernel(const float4* __restrict__ x) {
    const size_t n4 = (size_t)N_TOKENS * F_DIM / 4;
    uint2* hp = (uint2*)g_Xh;
    uint2* lp = (uint2*)g_Xl;
    for (size_t i = (size_t)blockIdx.x * blockDim.x + threadIdx.x; i < n4;
         i += (size_t)gridDim.x * blockDim.x) {
        float4 v = x[i];
        uint32_t h01, l01, h23, l23;
        split_pair(v.x, v.y, h01, l01);
        split_pair(v.z, v.w, h23, l23);
        hp[i] = make_uint2(h01, h23);
        lp[i] = make_uint2(l01, l23);
    }
}

// ---------------- output zero-init -------------------------------------------
__global__ void zero_out_kernel(float* __restrict__ out) {
    size_t idx = (size_t)blockIdx.x * blockDim.x + threadIdx.x;
    size_t n4 = (size_t)N_TOKENS * F_DIM / 4;
    float4 z = make_float4(0.f, 0.f, 0.f, 0.f);
    for (size_t i = idx; i < n4; i += (size_t)gridDim.x * blockDim.x)
        reinterpret_cast<float4*>(out)[i] = z;
}

// ---------------- router ------------------------------------------------------
__global__ void router_kernel(const float* __restrict__ x,
                              const float* __restrict__ gw) {
    const int t = blockIdx.x;
    const float* xr = x + (size_t)t * F_DIM;
    float p[N_EXP];
#pragma unroll
    for (int e = 0; e < N_EXP; e++) p[e] = 0.f;
    for (int i = threadIdx.x; i < F_DIM; i += blockDim.x) {
        float xv = xr[i];
#pragma unroll
        for (int e = 0; e < N_EXP; e++) p[e] += xv * gw[e * F_DIM + i];
    }
    __shared__ float red[N_EXP][128];
#pragma unroll
    for (int e = 0; e < N_EXP; e++) red[e][threadIdx.x] = p[e];
    __syncthreads();
    for (int s = 64; s > 0; s >>= 1) {
        if (threadIdx.x < s) {
#pragma unroll
            for (int e = 0; e < N_EXP; e++)
                red[e][threadIdx.x] += red[e][threadIdx.x + s];
        }
        __syncthreads();
    }
    if (threadIdx.x == 0) {
        float l[N_EXP];
#pragma unroll
        for (int e = 0; e < N_EXP; e++) l[e] = red[e][0];
        int e1 = 0;
#pragma unroll
        for (int e = 1; e < N_EXP; e++) if (l[e] > l[e1]) e1 = e;
        int e2 = (e1 == 0) ? 1 : 0;
#pragma unroll
        for (int e = 0; e < N_EXP; e++)
            if (e != e1 && l[e] > l[e2]) e2 = e;
        float d  = l[e2] - l[e1];
        float eb = expf(d);
        g_topk_idx[2 * t + 0] = e1;
        g_topk_idx[2 * t + 1] = e2;
        g_topk_w[2 * t + 0] = 1.f / (1.f + eb);
        g_topk_w[2 * t + 1] = eb / (1.f + eb);
    }
}

// ---------------- deterministic compaction -----------------------------------
__global__ void compact_kernel() {
    const int e = blockIdx.x;
    const int t = threadIdx.x;
    const int T0 = t * (N_TOKENS / 256);
    int flags[N_TOKENS / 256];
    int c = 0;
#pragma unroll
    for (int i = 0; i < N_TOKENS / 256; i++) {
        int tok = T0 + i;
        int f = -1;
        if (g_topk_idx[2 * tok + 0] == e) f = 0;
        else if (g_topk_idx[2 * tok + 1] == e) f = 1;
        flags[i] = f;
        if (f >= 0) c++;
    }
    __shared__ int s[256];
    s[t] = c;
    __syncthreads();
    for (int off = 1; off < 256; off <<= 1) {
        int v = (t >= off) ? s[t - off] : 0;
        __syncthreads();
        s[t] += v;
        __syncthreads();
    }
    int pos = e * SEG + (s[t] - c);
#pragma unroll
    for (int i = 0; i < N_TOKENS / 256; i++) {
        int f = flags[i];
        if (f >= 0) {
            int tok = T0 + i;
            g_pair_token[pos] = tok;
            g_pair_w[pos] = g_topk_w[2 * tok + f];
            pos++;
        }
    }
    if (t == 255) g_count[e] = s[255];
}

// ============================================================================
// Tile geometry: block M=128, N=128, K-chunk 32; 8 warps as 2M x 4N
//   A tile : [128 m][32 k] bf16, row stride 80 B  -> 10240 B/plane
//   B tile : [32 k][128 n] bf16, row stride 272 B ->  8704 B/plane
// ============================================================================
#define SA_STRIDE 80
#define SB_STRIDE 272

#define G1_AH    0
#define G1_AL    10240
#define G1_B1H   20480
#define G1_B1L   29184
#define G1_B3H   37888
#define G1_B3L   46592
#define G1_STAGE 55296
#define G1_SMEM  (3 * G1_STAGE)
#define NC1 (F_DIM / 32)

#define G2_AH    0
#define G2_AL    10240
#define G2_BH    20480
#define G2_BL    29184
#define G2_STAGE 37888
#define G2_SMEM  (3 * G2_STAGE)
#define NC2 (H_DIM / 32)

// ---------------- stage loaders ----------------------------------------------
__device__ __forceinline__ void g1_load(uint32_t db, int k0, int tid,
                                        int tok0, int tok1, int e, int n0) {
    // A: 2 planes x 128 rows x 4 chunks of 16B  (4 cp / thread)
#pragma unroll
    for (int i = 0; i < 4; i++) {
        int p  = i >> 1;
        int rr = ((i & 1) << 6) + (tid >> 2);
        int q  = tid & 3;
        int tk = (i & 1) ? tok1 : tok0;
        const __nv_bfloat16* sp = (p ? g_Xl : g_Xh) + (size_t)tk * F_DIM + k0 + q * 8;
        CP16(db + (p ? G1_AL : G1_AH) + rr * SA_STRIDE + q * 16, sp);
    }
    // B: 4 planes x 32 rows x 16 chunks of 16B  (8 cp / thread)
    const __nv_bfloat16* srcs[4];
    srcs[0] = g_W1h; srcs[1] = g_W1l; srcs[2] = g_W3h; srcs[3] = g_W3l;
    const uint32_t offs[4] = {G1_B1H, G1_B1L, G1_B3H, G1_B3L};
#pragma unroll
    for (int i = 0; i < 8; i++) {
        const int p = i >> 1;
        int r = ((i & 1) << 4) + (tid >> 4);
        int q = tid & 15;
        size_t base = ((size_t)e * F_DIM + k0 + r) * H_DIM + n0 + q * 8;
        CP16(db + offs[p] + r * SB_STRIDE + q * 16, srcs[p] + base);
    }
}

__device__ __forceinline__ void g2_load(uint32_t db, int k0, int tid,
                                        int e, int m0, int n0) {
#pragma unroll
    for (int i = 0; i < 4; i++) {
        int p  = i >> 1;
        int rr = ((i & 1) << 6) + (tid >> 2);
        int q  = tid & 3;
        const __nv_bfloat16* sp = (p ? g_Hl : g_Hh)
            + (size_t)(e * SEG + m0 + rr) * H_DIM + k0 + q * 8;
        CP16(db + (p ? G2_AL : G2_AH) + rr * SA_STRIDE + q * 16, sp);
    }
    const __nv_bfloat16* srcs[2];
    srcs[0] = g_W2h; srcs[1] = g_W2l;
    const uint32_t offs[2] = {G2_BH, G2_BL};
#pragma unroll
    for (int i = 0; i < 4; i++) {
        const int p = i >> 1;
        int r = ((i & 1) << 4) + (tid >> 4);
        int q = tid & 15;
        size_t base = ((size_t)e * H_DIM + k0 + r) * F_DIM + n0 + q * 8;
        CP16(db + offs[p] + r * SB_STRIDE + q * 16, srcs[p] + base);
    }
}

// ============================================================================
// GEMM1: D1 = Xg @ w1[:, n0:n0+128], D3 = Xg @ w3[...]; H = silu(D1)*D3
// ============================================================================
__global__ __launch_bounds__(256, 1)
void gemm1_mma(int dummy) {
    const int e = blockIdx.z;
    const int cnt = g_count[e];
    const int m0 = blockIdx.y * 128;
    if (m0 >= cnt) return;
    const int n0 = blockIdx.x * 128;

    extern __shared__ char dsm[];
    const uint32_t sb = smem_u32(dsm);

    const int tid = threadIdx.x;
    const int wid = tid >> 5;
    const int lane = tid & 31;
    const int mw = wid & 1;     // 2 M-warps (64 rows each)
    const int nw = wid >> 1;    // 4 N-warps (32 cols each)

    const int rr0 = tid >> 2;
    const int rr1 = 64 + rr0;
    int tok0 = g_pair_token[e * SEG + m0 + rr0]; if (m0 + rr0 >= cnt) tok0 = 0;
    int tok1 = g_pair_token[e * SEG + m0 + rr1]; if (m0 + rr1 >= cnt) tok1 = 0;

    const int j  = lane >> 3;
    const int rA = lane & 7;
    const uint32_t aRow  = (mw * 64 + (j & 1) * 8 + rA) * SA_STRIDE + ((j >> 1) * 8) * 2;
    const uint32_t bBase = ((j & 1) * 8 + rA) * SB_STRIDE + (nw * 32 + (j >> 1) * 8) * 2;

    float acc1[4][4][4], acc3[4][4][4];
#pragma unroll
    for (int mt = 0; mt < 4; mt++)
#pragma unroll
        for (int nt = 0; nt < 4; nt++)
#pragma unroll
            for (int k = 0; k < 4; k++) { acc1[mt][nt][k] = 0.f; acc3[mt][nt][k] = 0.f; }

    g1_load(sb, 0, tid, tok0, tok1, e, n0);
    CP_COMMIT();
    g1_load(sb + G1_STAGE, 32, tid, tok0, tok1, e, n0);
    CP_COMMIT();

    for (int c = 0; c < NC1; c++) {
        if (c == NC1 - 1) { CP_WAIT0(); } else { CP_WAIT1(); }
        __syncthreads();
        if (c + 2 < NC1) {
            g1_load(sb + ((c + 2) % 3) * G1_STAGE, (c + 2) * 32, tid, tok0, tok1, e, n0);
            CP_COMMIT();
        }

        const uint32_t tb = sb + (c % 3) * G1_STAGE;
#pragma unroll
        for (int kk = 0; kk < 32; kk += 16) {
            uint32_t aH[4][4], aL[4][4];
#pragma unroll
            for (int mt = 0; mt < 4; mt++) {
                ldsm_x4(tb + G1_AH + aRow + mt * (16 * SA_STRIDE) + kk * 2, aH[mt]);
                ldsm_x4(tb + G1_AL + aRow + mt * (16 * SA_STRIDE) + kk * 2, aL[mt]);
            }
            uint32_t bH[8], bL[8];
            // ---- w1 planes ----
            ldsm_x4_t(tb + G1_B1H + bBase + kk * SB_STRIDE,      bH);
            ldsm_x4_t(tb + G1_B1H + bBase + kk * SB_STRIDE + 32, bH + 4);
            ldsm_x4_t(tb + G1_B1L + bBase + kk * SB_STRIDE,      bL);
            ldsm_x4_t(tb + G1_B1L + bBase + kk * SB_STRIDE + 32, bL + 4);
#pragma unroll
            for (int mt = 0; mt < 4; mt++)
#pragma unroll
                for (int nt = 0; nt < 4; nt++) {
                    mma_bf16(acc1[mt][nt], aH[mt], bH + nt * 2);
                    mma_bf16(acc1[mt][nt], aL[mt], bH + nt * 2);
                    mma_bf16(acc1[mt][nt], aH[mt], bL + nt * 2);
                }
            // ---- w3 planes ----
            ldsm_x4_t(tb + G1_B3H + bBase + kk * SB_STRIDE,      bH);
            ldsm_x4_t(tb + G1_B3H + bBase + kk * SB_STRIDE + 32, bH + 4);
            ldsm_x4_t(tb + G1_B3L + bBase + kk * SB_STRIDE,      bL);
            ldsm_x4_t(tb + G1_B3L + bBase + kk * SB_STRIDE + 32, bL + 4);
#pragma unroll
            for (int mt = 0; mt < 4; mt++)
#pragma unroll
                for (int nt = 0; nt < 4; nt++) {
                    mma_bf16(acc3[mt][nt], aH[mt], bH + nt * 2);
                    mma_bf16(acc3[mt][nt], aL[mt], bH + nt * 2);
                    mma_bf16(acc3[mt][nt], aH[mt], bL + nt * 2);
                }
        }
        __syncthreads();
    }

    // epilogue: silu(D1)*D3 -> bf16 hi/lo H
#pragma unroll
    for (int mt = 0; mt < 4; mt++) {
        const int rbase = mw * 64 + mt * 16 + (lane >> 2);
#pragma unroll
        for (int half = 0; half < 2; half++) {
            const int r = rbase + half * 8;
            if (m0 + r < cnt) {
                const size_t rowoff = (size_t)(e * SEG + m0 + r) * H_DIM;
#pragma unroll
                for (int nt = 0; nt < 4; nt++) {
                    const int colg = n0 + nw * 32 + nt * 8 + 2 * (lane & 3);
                    float a0 = acc1[mt][nt][half * 2 + 0];
                    float a1 = acc1[mt][nt][half * 2 + 1];
                    float g0 = acc3[mt][nt][half * 2 + 0];
                    float g1 = acc3[mt][nt][half * 2 + 1];
                    float y0 = a0 / (1.f + expf(-a0)) * g0;
                    float y1 = a1 / (1.f + expf(-a1)) * g1;
                    uint32_t hi, lo;
                    split_pair(y0, y1, hi, lo);
                    *reinterpret_cast<uint32_t*>(g_Hh + rowoff + colg) = hi;
                    *reinterpret_cast<uint32_t*>(g_Hl + rowoff + colg) = lo;
                }
            }
        }
    }
}

// ============================================================================
// GEMM2: out[tok] += w * (H @ w2[:, n0:n0+128])
// ============================================================================
__global__ __launch_bounds__(256, 1)
void gemm2_mma(float* __restrict__ out) {
    const int e = blockIdx.z;
    const int cnt = g_count[e];
    const int m0 = blockIdx.y * 128;
    if (m0 >= cnt) return;
    const int n0 = blockIdx.x * 128;

    extern __shared__ char dsm[];
    const uint32_t sb = smem_u32(dsm);

    const int tid = threadIdx.x;
    const int wid = tid >> 5;
    const int lane = tid & 31;
    const int mw = wid & 1;
    const int nw = wid >> 1;

    const int j  = lane >> 3;
    const int rA = lane & 7;
    const uint32_t aRow  = (mw * 64 + (j & 1) * 8 + rA) * SA_STRIDE + ((j >> 1) * 8) * 2;
    const uint32_t bBase = ((j & 1) * 8 + rA) * SB_STRIDE + (nw * 32 + (j >> 1) * 8) * 2;

    float acc[4][4][4];
#pragma unroll
    for (int mt = 0; mt < 4; mt++)
#pragma unroll
        for (int nt = 0; nt < 4; nt++)
#pragma unroll
            for (int k = 0; k < 4; k++) acc[mt][nt][k] = 0.f;

    g2_load(sb, 0, tid, e, m0, n0);
    CP_COMMIT();
    g2_load(sb + G2_STAGE, 32, tid, e, m0, n0);
    CP_COMMIT();

    for (int c = 0; c < NC2; c++) {
        if (c == NC2 - 1) { CP_WAIT0(); } else { CP_WAIT1(); }
        __syncthreads();
        if (c + 2 < NC2) {
            g2_load(sb + ((c + 2) % 3) * G2_STAGE, (c + 2) * 32, tid, e, m0, n0);
            CP_COMMIT();
        }

        const uint32_t tb = sb + (c % 3) * G2_STAGE;
#pragma unroll
        for (int kk = 0; kk < 32; kk += 16) {
            uint32_t aH[4][4], aL[4][4];
#pragma unroll
            for (int mt = 0; mt < 4; mt++) {
                ldsm_x4(tb + G2_AH + aRow + mt * (16 * SA_STRIDE) + kk * 2, aH[mt]);
                ldsm_x4(tb + G2_AL + aRow + mt * (16 * SA_STRIDE) + kk * 2, aL[mt]);
            }
            uint32_t bH[8], bL[8];
            ldsm_x4_t(tb + G2_BH + bBase + kk * SB_STRIDE,      bH);
            ldsm_x4_t(tb + G2_BH + bBase + kk * SB_STRIDE + 32, bH + 4);
            ldsm_x4_t(tb + G2_BL + bBase + kk * SB_STRIDE,      bL);
            ldsm_x4_t(tb + G2_BL + bBase + kk * SB_STRIDE + 32, bL + 4);
#pragma unroll
            for (int mt = 0; mt < 4; mt++)
#pragma unroll
                for (int nt = 0; nt < 4; nt++) {
                    mma_bf16(acc[mt][nt], aH[mt], bH + nt * 2);
                    mma_bf16(acc[mt][nt], aL[mt], bH + nt * 2);
                    mma_bf16(acc[mt][nt], aH[mt], bL + nt * 2);
                }
        }
        __syncthreads();
    }

    // epilogue: weighted atomic scatter
#pragma unroll
    for (int mt = 0; mt < 4; mt++) {
        const int rbase = mw * 64 + mt * 16 + (lane >> 2);
#pragma unroll
        for (int half = 0; half < 2; half++) {
            const int r = rbase + half * 8;
            if (m0 + r < cnt) {
                const int tok = g_pair_token[e * SEG + m0 + r];
                const float wgt = g_pair_w[e * SEG + m0 + r];
                float* ob = out + (size_t)tok * F_DIM;
#pragma unroll
                for (int nt = 0; nt < 4; nt++) {
                    const int colg = n0 + nw * 32 + nt * 8 + 2 * (lane & 3);
                    atomicAdd(ob + colg,     wgt * acc[mt][nt][half * 2 + 0]);
                    atomicAdd(ob + colg + 1, wgt * acc[mt][nt][half * 2 + 1]);
                }
            }
        }
    }
}

// ---------------- launch ------------------------------------------------------
extern "C" void kernel_launch(void* const* d_in, const int* in_sizes, int n_in,
                              void* d_out, int out_size) {
    const float* x  = (const float*)d_in[0];
    const float* gw = (const float*)d_in[1];
    const float* w1 = (const float*)d_in[2];
    const float* w2 = (const float*)d_in[3];
    const float* w3 = (const float*)d_in[4];
    float* out = (float*)d_out;

    cudaFuncSetAttribute(gemm1_mma, cudaFuncAttributeMaxDynamicSharedMemorySize, G1_SMEM);
    cudaFuncSetAttribute(gemm2_mma, cudaFuncAttributeMaxDynamicSharedMemorySize, G2_SMEM);

    zero_out_kernel<<<512, 256>>>(out);
    prep_x_kernel<<<2048, 256>>>((const float4*)x);
    prep_w_kernel<<<dim3(4096, 3), 256>>>((const float4*)w1, (const float4*)w2,
                                          (const float4*)w3);
    router_kernel<<<N_TOKENS, 128>>>(x, gw);
    compact_kernel<<<N_EXP, 256>>>();
    gemm1_mma<<<dim3(H_DIM / 128, SEG / 128, N_EXP), 256, G1_SMEM>>>(0);
    gemm2_mma<<<dim3(F_DIM / 128, SEG / 128, N_EXP), 256, G2_SMEM>>>(out);
}

// round 13
// speedup vs baseline: 1.0415x; 1.0415x over previous
#include <cuda_runtime.h>
#include <cuda_bf16.h>
#include <cstdint>
#include <math.h>

// Problem constants
#define N_TOKENS 2048
#define F_DIM    2048
#define H_DIM    4096
#define N_EXP    8
#define SEG      2048

// ---------------- device scratch (static globals) ---------------------------
__device__ int   g_topk_idx[N_TOKENS * 2];
__device__ float g_topk_w[N_TOKENS * 2];
__device__ int   g_pair_token[N_EXP * SEG];
__device__ float g_pair_w[N_EXP * SEG];
__device__ int   g_count[N_EXP];

// bf16 hi/lo planes for x and H only (weights converted in-kernel now)
__device__ __align__(16) __nv_bfloat16 g_Xh[(size_t)N_TOKENS * F_DIM];
__device__ __align__(16) __nv_bfloat16 g_Xl[(size_t)N_TOKENS * F_DIM];
__device__ __align__(16) __nv_bfloat16 g_Hh[(size_t)N_EXP * SEG * H_DIM];
__device__ __align__(16) __nv_bfloat16 g_Hl[(size_t)N_EXP * SEG * H_DIM];

// ---------------- PTX helpers ------------------------------------------------
__device__ __forceinline__ uint32_t smem_u32(const void* p) {
    uint32_t a;
    asm("{ .reg .u64 t; cvta.to.shared.u64 t, %1; cvt.u32.u64 %0, t; }" : "=r"(a) : "l"(p));
    return a;
}

#define CP16(dst, src) \
    asm volatile("cp.async.cg.shared.global [%0], [%1], 16;" \
                 :: "r"(dst), "l"(src) : "memory")
#define CP_COMMIT() asm volatile("cp.async.commit_group;" ::: "memory")
#define CP_WAIT0()  asm volatile("cp.async.wait_group 0;" ::: "memory")
#define CP_WAIT1()  asm volatile("cp.async.wait_group 1;" ::: "memory")

__device__ __forceinline__ void ldsm_x4(uint32_t addr, uint32_t* r) {
    asm volatile("ldmatrix.sync.aligned.m8n8.x4.shared.b16 {%0,%1,%2,%3}, [%4];"
                 : "=r"(r[0]), "=r"(r[1]), "=r"(r[2]), "=r"(r[3]) : "r"(addr));
}
__device__ __forceinline__ void ldsm_x4_t(uint32_t addr, uint32_t* r) {
    asm volatile("ldmatrix.sync.aligned.m8n8.x4.trans.shared.b16 {%0,%1,%2,%3}, [%4];"
                 : "=r"(r[0]), "=r"(r[1]), "=r"(r[2]), "=r"(r[3]) : "r"(addr));
}
__device__ __forceinline__ void mma_bf16(float* d, const uint32_t* a, const uint32_t* b) {
    asm volatile(
        "mma.sync.aligned.m16n8k16.row.col.f32.bf16.bf16.f32 "
        "{%0,%1,%2,%3}, {%4,%5,%6,%7}, {%8,%9}, {%0,%1,%2,%3};"
        : "+f"(d[0]), "+f"(d[1]), "+f"(d[2]), "+f"(d[3])
        : "r"(a[0]), "r"(a[1]), "r"(a[2]), "r"(a[3]), "r"(b[0]), "r"(b[1]));
}

__device__ __forceinline__ void split_pair(float y0, float y1, uint32_t& hi, uint32_t& lo) {
    uint32_t u0 = __float_as_uint(y0), u1 = __float_as_uint(y1);
    hi = __byte_perm(u0, u1, 0x7632);
    float l0 = y0 - __uint_as_float(u0 & 0xffff0000u);
    float l1 = y1 - __uint_as_float(u1 & 0xffff0000u);
    lo = __byte_perm(__float_as_uint(l0), __float_as_uint(l1), 0x7632);
}

// ---------------- preprocessing: x only --------------------------------------
__global__ void prep_x_kernel(const float4* __restrict__ x) {
    const size_t n4 = (size_t)N_TOKENS * F_DIM / 4;
    uint2* hp = (uint2*)g_Xh;
    uint2* lp = (uint2*)g_Xl;
    for (size_t i = (size_t)blockIdx.x * blockDim.x + threadIdx.x; i < n4;
         i += (size_t)gridDim.x * blockDim.x) {
        float4 v = x[i];
        uint32_t h01, l01, h23, l23;
        split_pair(v.x, v.y, h01, l01);
        split_pair(v.z, v.w, h23, l23);
        hp[i] = make_uint2(h01, h23);
        lp[i] = make_uint2(l01, l23);
    }
}

// ---------------- output zero-init -------------------------------------------
__global__ void zero_out_kernel(float* __restrict__ out) {
    size_t idx = (size_t)blockIdx.x * blockDim.x + threadIdx.x;
    size_t n4 = (size_t)N_TOKENS * F_DIM / 4;
    float4 z = make_float4(0.f, 0.f, 0.f, 0.f);
    for (size_t i = idx; i < n4; i += (size_t)gridDim.x * blockDim.x)
        reinterpret_cast<float4*>(out)[i] = z;
}

// ---------------- router ------------------------------------------------------
__global__ void router_kernel(const float* __restrict__ x,
                              const float* __restrict__ gw) {
    const int t = blockIdx.x;
    const float* xr = x + (size_t)t * F_DIM;
    float p[N_EXP];
#pragma unroll
    for (int e = 0; e < N_EXP; e++) p[e] = 0.f;
    for (int i = threadIdx.x; i < F_DIM; i += blockDim.x) {
        float xv = xr[i];
#pragma unroll
        for (int e = 0; e < N_EXP; e++) p[e] += xv * gw[e * F_DIM + i];
    }
    __shared__ float red[N_EXP][128];
#pragma unroll
    for (int e = 0; e < N_EXP; e++) red[e][threadIdx.x] = p[e];
    __syncthreads();
    for (int s = 64; s > 0; s >>= 1) {
        if (threadIdx.x < s) {
#pragma unroll
            for (int e = 0; e < N_EXP; e++)
                red[e][threadIdx.x] += red[e][threadIdx.x + s];
        }
        __syncthreads();
    }
    if (threadIdx.x == 0) {
        float l[N_EXP];
#pragma unroll
        for (int e = 0; e < N_EXP; e++) l[e] = red[e][0];
        int e1 = 0;
#pragma unroll
        for (int e = 1; e < N_EXP; e++) if (l[e] > l[e1]) e1 = e;
        int e2 = (e1 == 0) ? 1 : 0;
#pragma unroll
        for (int e = 0; e < N_EXP; e++)
            if (e != e1 && l[e] > l[e2]) e2 = e;
        float d  = l[e2] - l[e1];
        float eb = expf(d);
        g_topk_idx[2 * t + 0] = e1;
        g_topk_idx[2 * t + 1] = e2;
        g_topk_w[2 * t + 0] = 1.f / (1.f + eb);
        g_topk_w[2 * t + 1] = eb / (1.f + eb);
    }
}

// ---------------- deterministic compaction -----------------------------------
__global__ void compact_kernel() {
    const int e = blockIdx.x;
    const int t = threadIdx.x;
    const int T0 = t * (N_TOKENS / 256);
    int flags[N_TOKENS / 256];
    int c = 0;
#pragma unroll
    for (int i = 0; i < N_TOKENS / 256; i++) {
        int tok = T0 + i;
        int f = -1;
        if (g_topk_idx[2 * tok + 0] == e) f = 0;
        else if (g_topk_idx[2 * tok + 1] == e) f = 1;
        flags[i] = f;
        if (f >= 0) c++;
    }
    __shared__ int s[256];
    s[t] = c;
    __syncthreads();
    for (int off = 1; off < 256; off <<= 1) {
        int v = (t >= off) ? s[t - off] : 0;
        __syncthreads();
        s[t] += v;
        __syncthreads();
    }
    int pos = e * SEG + (s[t] - c);
#pragma unroll
    for (int i = 0; i < N_TOKENS / 256; i++) {
        int f = flags[i];
        if (f >= 0) {
            int tok = T0 + i;
            g_pair_token[pos] = tok;
            g_pair_w[pos] = g_topk_w[2 * tok + f];
            pos++;
        }
    }
    if (t == 255) g_count[e] = s[255];
}

// ============================================================================
// Tile geometry: block M=128, N=128, K-chunk 32; 8 warps as 2M x 4N
//   A tile : [128 m][32 k] bf16, row stride 80 B  -> 10240 B/plane
//   B tile : [32 k][128 n] bf16, row stride 272 B ->  8704 B/plane
//   B staging: raw fp32 [mats][32 k][128 n] flat (converted in-kernel)
// ============================================================================
#define SA_STRIDE 80
#define SB_STRIDE 272

#define G1_AH    0
#define G1_AL    10240
#define G1_B1H   20480
#define G1_B1L   29184
#define G1_B3H   37888
#define G1_B3L   46592
#define G1_ST    55296
#define G1_STAGE 88064
#define G1_SMEM  (2 * G1_STAGE)
#define NC1 (F_DIM / 32)

#define G2_AH    0
#define G2_AL    10240
#define G2_BH    20480
#define G2_BL    29184
#define G2_ST    37888
#define G2_STAGE 54272
#define G2_SMEM  (2 * G2_STAGE)
#define NC2 (H_DIM / 32)

// ---------------- stage loaders (raw fp32 B into staging) --------------------
__device__ __forceinline__ void g1_load(uint32_t db, int k0, int tid,
                                        int tok0, int tok1, int e, int n0,
                                        const float* __restrict__ w1,
                                        const float* __restrict__ w3) {
    // A: 2 planes x 128 rows x 4 chunks of 16B (4 cp / thread), prepped bf16
#pragma unroll
    for (int i = 0; i < 4; i++) {
        int p  = i >> 1;
        int rr = ((i & 1) << 6) + (tid >> 2);
        int q  = tid & 3;
        int tk = (i & 1) ? tok1 : tok0;
        const __nv_bfloat16* sp = (p ? g_Xl : g_Xh) + (size_t)tk * F_DIM + k0 + q * 8;
        CP16(db + (p ? G1_AL : G1_AH) + rr * SA_STRIDE + q * 16, sp);
    }
    // B staging: raw fp32, flat [2][32][128] floats (8 cp / thread)
#pragma unroll
    for (int i = 0; i < 8; i++) {
        int f = tid + 256 * i;
        int mat = f >> 10;
        int rem = f & 1023;
        int r = rem >> 5;
        int q = rem & 31;
        const float* wp = (mat ? w3 : w1)
            + ((size_t)e * F_DIM + k0 + r) * H_DIM + n0 + q * 4;
        CP16(db + G1_ST + f * 16, wp);
    }
}

__device__ __forceinline__ void g2_load(uint32_t db, int k0, int tid,
                                        int e, int m0, int n0,
                                        const float* __restrict__ w2) {
#pragma unroll
    for (int i = 0; i < 4; i++) {
        int p  = i >> 1;
        int rr = ((i & 1) << 6) + (tid >> 2);
        int q  = tid & 3;
        const __nv_bfloat16* sp = (p ? g_Hl : g_Hh)
            + (size_t)(e * SEG + m0 + rr) * H_DIM + k0 + q * 8;
        CP16(db + (p ? G2_AL : G2_AH) + rr * SA_STRIDE + q * 16, sp);
    }
    // B staging: raw fp32, flat [32][128] floats (4 cp / thread)
#pragma unroll
    for (int i = 0; i < 4; i++) {
        int f = tid + 256 * i;
        int r = f >> 5;
        int q = f & 31;
        const float* wp = w2 + ((size_t)e * H_DIM + k0 + r) * F_DIM + n0 + q * 4;
        CP16(db + G2_ST + f * 16, wp);
    }
}

// ---------------- in-kernel converters: staging fp32 -> bf16 hi/lo tiles -----
__device__ __forceinline__ void g1_convert(char* stage, int tid) {
    const char* stg = stage + G1_ST;
#pragma unroll
    for (int i = 0; i < 8; i++) {
        int f = tid + 256 * i;
        int mat = f >> 10;
        int r = (f >> 5) & 31;
        int q = f & 31;
        float4 v = *reinterpret_cast<const float4*>(stg + f * 16);
        uint32_t h01, l01, h23, l23;
        split_pair(v.x, v.y, h01, l01);
        split_pair(v.z, v.w, h23, l23);
        uint32_t doff = r * SB_STRIDE + q * 8;
        char* hB = stage + (mat ? G1_B3H : G1_B1H);
        char* lB = stage + (mat ? G1_B3L : G1_B1L);
        *reinterpret_cast<uint2*>(hB + doff) = make_uint2(h01, h23);
        *reinterpret_cast<uint2*>(lB + doff) = make_uint2(l01, l23);
    }
}

__device__ __forceinline__ void g2_convert(char* stage, int tid) {
    const char* stg = stage + G2_ST;
#pragma unroll
    for (int i = 0; i < 4; i++) {
        int f = tid + 256 * i;
        int r = f >> 5;
        int q = f & 31;
        float4 v = *reinterpret_cast<const float4*>(stg + f * 16);
        uint32_t h01, l01, h23, l23;
        split_pair(v.x, v.y, h01, l01);
        split_pair(v.z, v.w, h23, l23);
        uint32_t doff = r * SB_STRIDE + q * 8;
        *reinterpret_cast<uint2*>(stage + G2_BH + doff) = make_uint2(h01, h23);
        *reinterpret_cast<uint2*>(stage + G2_BL + doff) = make_uint2(l01, l23);
    }
}

// ============================================================================
// GEMM1: D1 = Xg @ w1[:, n0:n0+128], D3 = Xg @ w3[...]; H = silu(D1)*D3
// ============================================================================
__global__ __launch_bounds__(256, 1)
void gemm1_mma(const float* __restrict__ w1, const float* __restrict__ w3) {
    const int e = blockIdx.z;
    const int cnt = g_count[e];
    const int m0 = blockIdx.y * 128;
    if (m0 >= cnt) return;
    const int n0 = blockIdx.x * 128;

    extern __shared__ char dsm[];
    const uint32_t sb = smem_u32(dsm);

    const int tid = threadIdx.x;
    const int wid = tid >> 5;
    const int lane = tid & 31;
    const int mw = wid & 1;     // 2 M-warps (64 rows each)
    const int nw = wid >> 1;    // 4 N-warps (32 cols each)

    const int rr0 = tid >> 2;
    const int rr1 = 64 + rr0;
    int tok0 = g_pair_token[e * SEG + m0 + rr0]; if (m0 + rr0 >= cnt) tok0 = 0;
    int tok1 = g_pair_token[e * SEG + m0 + rr1]; if (m0 + rr1 >= cnt) tok1 = 0;

    const int j  = lane >> 3;
    const int rA = lane & 7;
    const uint32_t aRow  = (mw * 64 + (j & 1) * 8 + rA) * SA_STRIDE + ((j >> 1) * 8) * 2;
    const uint32_t bBase = ((j & 1) * 8 + rA) * SB_STRIDE + (nw * 32 + (j >> 1) * 8) * 2;

    float acc1[4][4][4], acc3[4][4][4];
#pragma unroll
    for (int mt = 0; mt < 4; mt++)
#pragma unroll
        for (int nt = 0; nt < 4; nt++)
#pragma unroll
            for (int k = 0; k < 4; k++) { acc1[mt][nt][k] = 0.f; acc3[mt][nt][k] = 0.f; }

    g1_load(sb, 0, tid, tok0, tok1, e, n0, w1, w3);
    CP_COMMIT();

    for (int c = 0; c < NC1; c++) {
        if (c + 1 < NC1) {
            g1_load(sb + ((c + 1) & 1) * G1_STAGE, (c + 1) * 32, tid,
                    tok0, tok1, e, n0, w1, w3);
            CP_COMMIT();
            CP_WAIT1();
        } else {
            CP_WAIT0();
        }
        __syncthreads();
        g1_convert(dsm + (c & 1) * G1_STAGE, tid);
        __syncthreads();

        const uint32_t tb = sb + (c & 1) * G1_STAGE;
#pragma unroll
        for (int kk = 0; kk < 32; kk += 16) {
            uint32_t aH[4][4], aL[4][4];
#pragma unroll
            for (int mt = 0; mt < 4; mt++) {
                ldsm_x4(tb + G1_AH + aRow + mt * (16 * SA_STRIDE) + kk * 2, aH[mt]);
                ldsm_x4(tb + G1_AL + aRow + mt * (16 * SA_STRIDE) + kk * 2, aL[mt]);
            }
            uint32_t bH[8], bL[8];
            // ---- w1 planes ----
            ldsm_x4_t(tb + G1_B1H + bBase + kk * SB_STRIDE,      bH);
            ldsm_x4_t(tb + G1_B1H + bBase + kk * SB_STRIDE + 32, bH + 4);
            ldsm_x4_t(tb + G1_B1L + bBase + kk * SB_STRIDE,      bL);
            ldsm_x4_t(tb + G1_B1L + bBase + kk * SB_STRIDE + 32, bL + 4);
#pragma unroll
            for (int mt = 0; mt < 4; mt++)
#pragma unroll
                for (int nt = 0; nt < 4; nt++) {
                    mma_bf16(acc1[mt][nt], aH[mt], bH + nt * 2);
                    mma_bf16(acc1[mt][nt], aL[mt], bH + nt * 2);
                    mma_bf16(acc1[mt][nt], aH[mt], bL + nt * 2);
                }
            // ---- w3 planes ----
            ldsm_x4_t(tb + G1_B3H + bBase + kk * SB_STRIDE,      bH);
            ldsm_x4_t(tb + G1_B3H + bBase + kk * SB_STRIDE + 32, bH + 4);
            ldsm_x4_t(tb + G1_B3L + bBase + kk * SB_STRIDE,      bL);
            ldsm_x4_t(tb + G1_B3L + bBase + kk * SB_STRIDE + 32, bL + 4);
#pragma unroll
            for (int mt = 0; mt < 4; mt++)
#pragma unroll
                for (int nt = 0; nt < 4; nt++) {
                    mma_bf16(acc3[mt][nt], aH[mt], bH + nt * 2);
                    mma_bf16(acc3[mt][nt], aL[mt], bH + nt * 2);
                    mma_bf16(acc3[mt][nt], aH[mt], bL + nt * 2);
                }
        }
        __syncthreads();
    }

    // epilogue: silu(D1)*D3 -> bf16 hi/lo H
#pragma unroll
    for (int mt = 0; mt < 4; mt++) {
        const int rbase = mw * 64 + mt * 16 + (lane >> 2);
#pragma unroll
        for (int half = 0; half < 2; half++) {
            const int r = rbase + half * 8;
            if (m0 + r < cnt) {
                const size_t rowoff = (size_t)(e * SEG + m0 + r) * H_DIM;
#pragma unroll
                for (int nt = 0; nt < 4; nt++) {
                    const int colg = n0 + nw * 32 + nt * 8 + 2 * (lane & 3);
                    float a0 = acc1[mt][nt][half * 2 + 0];
                    float a1 = acc1[mt][nt][half * 2 + 1];
                    float g0 = acc3[mt][nt][half * 2 + 0];
                    float g1 = acc3[mt][nt][half * 2 + 1];
                    float y0 = a0 / (1.f + expf(-a0)) * g0;
                    float y1 = a1 / (1.f + expf(-a1)) * g1;
                    uint32_t hi, lo;
                    split_pair(y0, y1, hi, lo);
                    *reinterpret_cast<uint32_t*>(g_Hh + rowoff + colg) = hi;
                    *reinterpret_cast<uint32_t*>(g_Hl + rowoff + colg) = lo;
                }
            }
        }
    }
}

// ============================================================================
// GEMM2: out[tok] += w * (H @ w2[:, n0:n0+128])
// ============================================================================
__global__ __launch_bounds__(256, 1)
void gemm2_mma(const float* __restrict__ w2, float* __restrict__ out) {
    const int e = blockIdx.z;
    const int cnt = g_count[e];
    const int m0 = blockIdx.y * 128;
    if (m0 >= cnt) return;
    const int n0 = blockIdx.x * 128;

    extern __shared__ char dsm[];
    const uint32_t sb = smem_u32(dsm);

    const int tid = threadIdx.x;
    const int wid = tid >> 5;
    const int lane = tid & 31;
    const int mw = wid & 1;
    const int nw = wid >> 1;

    const int j  = lane >> 3;
    const int rA = lane & 7;
    const uint32_t aRow  = (mw * 64 + (j & 1) * 8 + rA) * SA_STRIDE + ((j >> 1) * 8) * 2;
    const uint32_t bBase = ((j & 1) * 8 + rA) * SB_STRIDE + (nw * 32 + (j >> 1) * 8) * 2;

    float acc[4][4][4];
#pragma unroll
    for (int mt = 0; mt < 4; mt++)
#pragma unroll
        for (int nt = 0; nt < 4; nt++)
#pragma unroll
            for (int k = 0; k < 4; k++) acc[mt][nt][k] = 0.f;

    g2_load(sb, 0, tid, e, m0, n0, w2);
    CP_COMMIT();

    for (int c = 0; c < NC2; c++) {
        if (c + 1 < NC2) {
            g2_load(sb + ((c + 1) & 1) * G2_STAGE, (c + 1) * 32, tid, e, m0, n0, w2);
            CP_COMMIT();
            CP_WAIT1();
        } else {
            CP_WAIT0();
        }
        __syncthreads();
        g2_convert(dsm + (c & 1) * G2_STAGE, tid);
        __syncthreads();

        const uint32_t tb = sb + (c & 1) * G2_STAGE;
#pragma unroll
        for (int kk = 0; kk < 32; kk += 16) {
            uint32_t aH[4][4], aL[4][4];
#pragma unroll
            for (int mt = 0; mt < 4; mt++) {
                ldsm_x4(tb + G2_AH + aRow + mt * (16 * SA_STRIDE) + kk * 2, aH[mt]);
                ldsm_x4(tb + G2_AL + aRow + mt * (16 * SA_STRIDE) + kk * 2, aL[mt]);
            }
            uint32_t bH[8], bL[8];
            ldsm_x4_t(tb + G2_BH + bBase + kk * SB_STRIDE,      bH);
            ldsm_x4_t(tb + G2_BH + bBase + kk * SB_STRIDE + 32, bH + 4);
            ldsm_x4_t(tb + G2_BL + bBase + kk * SB_STRIDE,      bL);
            ldsm_x4_t(tb + G2_BL + bBase + kk * SB_STRIDE + 32, bL + 4);
#pragma unroll
            for (int mt = 0; mt < 4; mt++)
#pragma unroll
                for (int nt = 0; nt < 4; nt++) {
                    mma_bf16(acc[mt][nt], aH[mt], bH + nt * 2);
                    mma_bf16(acc[mt][nt], aL[mt], bH + nt * 2);
                    mma_bf16(acc[mt][nt], aH[mt], bL + nt * 2);
                }
        }
        __syncthreads();
    }

    // epilogue: weighted atomic scatter
#pragma unroll
    for (int mt = 0; mt < 4; mt++) {
        const int rbase = mw * 64 + mt * 16 + (lane >> 2);
#pragma unroll
        for (int half = 0; half < 2; half++) {
            const int r = rbase + half * 8;
            if (m0 + r < cnt) {
                const int tok = g_pair_token[e * SEG + m0 + r];
                const float wgt = g_pair_w[e * SEG + m0 + r];
                float* ob = out + (size_t)tok * F_DIM;
#pragma unroll
                for (int nt = 0; nt < 4; nt++) {
                    const int colg = n0 + nw * 32 + nt * 8 + 2 * (lane & 3);
                    atomicAdd(ob + colg,     wgt * acc[mt][nt][half * 2 + 0]);
                    atomicAdd(ob + colg + 1, wgt * acc[mt][nt][half * 2 + 1]);
                }
            }
        }
    }
}

// ---------------- launch ------------------------------------------------------
extern "C" void kernel_launch(void* const* d_in, const int* in_sizes, int n_in,
                              void* d_out, int out_size) {
    const float* x  = (const float*)d_in[0];
    const float* gw = (const float*)d_in[1];
    const float* w1 = (const float*)d_in[2];
    const float* w2 = (const float*)d_in[3];
    const float* w3 = (const float*)d_in[4];
    float* out = (float*)d_out;

    cudaFuncSetAttribute(gemm1_mma, cudaFuncAttributeMaxDynamicSharedMemorySize, G1_SMEM);
    cudaFuncSetAttribute(gemm2_mma, cudaFuncAttributeMaxDynamicSharedMemorySize, G2_SMEM);

    zero_out_kernel<<<512, 256>>>(out);
    prep_x_kernel<<<2048, 256>>>((const float4*)x);
    router_kernel<<<N_TOKENS, 128>>>(x, gw);
    compact_kernel<<<N_EXP, 256>>>();
    gemm1_mma<<<dim3(H_DIM / 128, SEG / 128, N_EXP), 256, G1_SMEM>>>(w1, w3);
    gemm2_mma<<<dim3(F_DIM / 128, SEG / 128, N_EXP), 256, G2_SMEM>>>(w2, out);
}

// round 14
// speedup vs baseline: 1.1285x; 1.0836x over previous
#include <cuda_runtime.h>
#include <cuda_bf16.h>
#include <cstdint>
#include <math.h>

// Problem constants
#define N_TOKENS 2048
#define F_DIM    2048
#define H_DIM    4096
#define N_EXP    8
#define SEG      2048

// ---------------- device scratch (static globals) ---------------------------
__device__ int   g_topk_idx[N_TOKENS * 2];
__device__ float g_topk_w[N_TOKENS * 2];
__device__ int   g_pair_token[N_EXP * SEG];
__device__ float g_pair_w[N_EXP * SEG];
__device__ int   g_count[N_EXP];

// bf16 hi/lo planes for x and H (weights converted in-kernel)
__device__ __align__(16) __nv_bfloat16 g_Xh[(size_t)N_TOKENS * F_DIM];
__device__ __align__(16) __nv_bfloat16 g_Xl[(size_t)N_TOKENS * F_DIM];
__device__ __align__(16) __nv_bfloat16 g_Hh[(size_t)N_EXP * SEG * H_DIM];
__device__ __align__(16) __nv_bfloat16 g_Hl[(size_t)N_EXP * SEG * H_DIM];

// ---------------- PTX helpers ------------------------------------------------
__device__ __forceinline__ uint32_t smem_u32(const void* p) {
    uint32_t a;
    asm("{ .reg .u64 t; cvta.to.shared.u64 t, %1; cvt.u32.u64 %0, t; }" : "=r"(a) : "l"(p));
    return a;
}

#define CP16(dst, src) \
    asm volatile("cp.async.cg.shared.global [%0], [%1], 16;" \
                 :: "r"(dst), "l"(src) : "memory")
#define CP_COMMIT() asm volatile("cp.async.commit_group;" ::: "memory")
#define CP_WAIT0()  asm volatile("cp.async.wait_group 0;" ::: "memory")

__device__ __forceinline__ void ldsm_x4(uint32_t addr, uint32_t* r) {
    asm volatile("ldmatrix.sync.aligned.m8n8.x4.shared.b16 {%0,%1,%2,%3}, [%4];"
                 : "=r"(r[0]), "=r"(r[1]), "=r"(r[2]), "=r"(r[3]) : "r"(addr));
}
__device__ __forceinline__ void ldsm_x4_t(uint32_t addr, uint32_t* r) {
    asm volatile("ldmatrix.sync.aligned.m8n8.x4.trans.shared.b16 {%0,%1,%2,%3}, [%4];"
                 : "=r"(r[0]), "=r"(r[1]), "=r"(r[2]), "=r"(r[3]) : "r"(addr));
}
__device__ __forceinline__ void mma_bf16(float* d, const uint32_t* a, const uint32_t* b) {
    asm volatile(
        "mma.sync.aligned.m16n8k16.row.col.f32.bf16.bf16.f32 "
        "{%0,%1,%2,%3}, {%4,%5,%6,%7}, {%8,%9}, {%0,%1,%2,%3};"
        : "+f"(d[0]), "+f"(d[1]), "+f"(d[2]), "+f"(d[3])
        : "r"(a[0]), "r"(a[1]), "r"(a[2]), "r"(a[3]), "r"(b[0]), "r"(b[1]));
}

__device__ __forceinline__ void split_pair(float y0, float y1, uint32_t& hi, uint32_t& lo) {
    uint32_t u0 = __float_as_uint(y0), u1 = __float_as_uint(y1);
    hi = __byte_perm(u0, u1, 0x7632);
    float l0 = y0 - __uint_as_float(u0 & 0xffff0000u);
    float l1 = y1 - __uint_as_float(u1 & 0xffff0000u);
    lo = __byte_perm(__float_as_uint(l0), __float_as_uint(l1), 0x7632);
}

// ---------------- output zero-init -------------------------------------------
__global__ void zero_out_kernel(float* __restrict__ out) {
    size_t idx = (size_t)blockIdx.x * blockDim.x + threadIdx.x;
    size_t n4 = (size_t)N_TOKENS * F_DIM / 4;
    float4 z = make_float4(0.f, 0.f, 0.f, 0.f);
    for (size_t i = idx; i < n4; i += (size_t)gridDim.x * blockDim.x)
        reinterpret_cast<float4*>(out)[i] = z;
}

// ---------------- router (also emits Xh/Xl split) ------------------------------
__global__ void router_kernel(const float* __restrict__ x,
                              const float* __restrict__ gw) {
    const int t = blockIdx.x;
    const float* xr = x + (size_t)t * F_DIM;
    uint16_t* xh = reinterpret_cast<uint16_t*>(g_Xh) + (size_t)t * F_DIM;
    uint16_t* xl = reinterpret_cast<uint16_t*>(g_Xl) + (size_t)t * F_DIM;
    float p[N_EXP];
#pragma unroll
    for (int e = 0; e < N_EXP; e++) p[e] = 0.f;
    for (int i = threadIdx.x; i < F_DIM; i += blockDim.x) {
        float xv = xr[i];
        uint32_t u = __float_as_uint(xv);
        xh[i] = (uint16_t)(u >> 16);
        float lo = xv - __uint_as_float(u & 0xffff0000u);
        xl[i] = (uint16_t)(__float_as_uint(lo) >> 16);
#pragma unroll
        for (int e = 0; e < N_EXP; e++) p[e] += xv * gw[e * F_DIM + i];
    }
    __shared__ float red[N_EXP][128];
#pragma unroll
    for (int e = 0; e < N_EXP; e++) red[e][threadIdx.x] = p[e];
    __syncthreads();
    for (int s = 64; s > 0; s >>= 1) {
        if (threadIdx.x < s) {
#pragma unroll
            for (int e = 0; e < N_EXP; e++)
                red[e][threadIdx.x] += red[e][threadIdx.x + s];
        }
        __syncthreads();
    }
    if (threadIdx.x == 0) {
        float l[N_EXP];
#pragma unroll
        for (int e = 0; e < N_EXP; e++) l[e] = red[e][0];
        int e1 = 0;
#pragma unroll
        for (int e = 1; e < N_EXP; e++) if (l[e] > l[e1]) e1 = e;
        int e2 = (e1 == 0) ? 1 : 0;
#pragma unroll
        for (int e = 0; e < N_EXP; e++)
            if (e != e1 && l[e] > l[e2]) e2 = e;
        float d  = l[e2] - l[e1];
        float eb = expf(d);
        g_topk_idx[2 * t + 0] = e1;
        g_topk_idx[2 * t + 1] = e2;
        g_topk_w[2 * t + 0] = 1.f / (1.f + eb);
        g_topk_w[2 * t + 1] = eb / (1.f + eb);
    }
}

// ---------------- deterministic compaction -----------------------------------
__global__ void compact_kernel() {
    const int e = blockIdx.x;
    const int t = threadIdx.x;
    const int T0 = t * (N_TOKENS / 256);
    int flags[N_TOKENS / 256];
    int c = 0;
#pragma unroll
    for (int i = 0; i < N_TOKENS / 256; i++) {
        int tok = T0 + i;
        int f = -1;
        if (g_topk_idx[2 * tok + 0] == e) f = 0;
        else if (g_topk_idx[2 * tok + 1] == e) f = 1;
        flags[i] = f;
        if (f >= 0) c++;
    }
    __shared__ int s[256];
    s[t] = c;
    __syncthreads();
    for (int off = 1; off < 256; off <<= 1) {
        int v = (t >= off) ? s[t - off] : 0;
        __syncthreads();
        s[t] += v;
        __syncthreads();
    }
    int pos = e * SEG + (s[t] - c);
#pragma unroll
    for (int i = 0; i < N_TOKENS / 256; i++) {
        int f = flags[i];
        if (f >= 0) {
            int tok = T0 + i;
            g_pair_token[pos] = tok;
            g_pair_w[pos] = g_topk_w[2 * tok + f];
            pos++;
        }
    }
    if (t == 255) g_count[e] = s[255];
}

// ============================================================================
// GEMM1 geometry: block M=128, N=128, K-chunk 32; 8 warps as 2M x 4N
//   A tile : [128 m][32 k] bf16, stride 80 B  -> 10240 B/plane
//   B tile : [32 k][128 n] bf16, stride 272 B ->  8704 B/plane
// GEMM2 geometry: K-chunk 64
//   A tile : [128 m][64 k] bf16, stride 144 B -> 18432 B/plane
//   B tile : [64 k][128 n] bf16, stride 272 B -> 17408 B/plane
// ============================================================================
#define SA1_STRIDE 80
#define SA2_STRIDE 144
#define SB_STRIDE  272

#define G1_AH    0
#define G1_AL    10240
#define G1_B1H   20480
#define G1_B1L   29184
#define G1_B3H   37888
#define G1_B3L   46592
#define G1_ST    55296
#define G1_STAGE 88064
#define G1_SMEM  (2 * G1_STAGE)
#define NC1 (F_DIM / 32)

#define G2_AH    0
#define G2_AL    18432
#define G2_BH    36864
#define G2_BL    54272
#define G2_ST    71680
#define G2_STAGE 104448
#define G2_SMEM  (2 * G2_STAGE)
#define NC2 (H_DIM / 64)

// ---------------- stage loaders -----------------------------------------------
__device__ __forceinline__ void g1_load(uint32_t db, int k0, int tid,
                                        int tok0, int tok1, int e, int n0,
                                        const float* __restrict__ w1,
                                        const float* __restrict__ w3) {
    // A: 2 planes x 128 rows x 4 chunks of 16B (4 cp / thread), prepped bf16
#pragma unroll
    for (int i = 0; i < 4; i++) {
        int p  = i >> 1;
        int rr = ((i & 1) << 6) + (tid >> 2);
        int q  = tid & 3;
        int tk = (i & 1) ? tok1 : tok0;
        const __nv_bfloat16* sp = (p ? g_Xl : g_Xh) + (size_t)tk * F_DIM + k0 + q * 8;
        CP16(db + (p ? G1_AL : G1_AH) + rr * SA1_STRIDE + q * 16, sp);
    }
    // B staging: raw fp32, flat [2][32][128] floats (8 cp / thread)
#pragma unroll
    for (int i = 0; i < 8; i++) {
        int f = tid + 256 * i;
        int mat = f >> 10;
        int rem = f & 1023;
        int r = rem >> 5;
        int q = rem & 31;
        const float* wp = (mat ? w3 : w1)
            + ((size_t)e * F_DIM + k0 + r) * H_DIM + n0 + q * 4;
        CP16(db + G1_ST + f * 16, wp);
    }
}

__device__ __forceinline__ void g2_load(uint32_t db, int k0, int tid,
                                        int e, int m0, int n0,
                                        const float* __restrict__ w2) {
    // A: 2 planes x 128 rows x 8 chunks of 16B (8 cp / thread)
#pragma unroll
    for (int i = 0; i < 8; i++) {
        int p  = i >> 2;
        int f  = tid + 256 * (i & 3);
        int rr = f >> 3;
        int q  = f & 7;
        const __nv_bfloat16* sp = (p ? g_Hl : g_Hh)
            + (size_t)(e * SEG + m0 + rr) * H_DIM + k0 + q * 8;
        CP16(db + (p ? G2_AL : G2_AH) + rr * SA2_STRIDE + q * 16, sp);
    }
    // B staging: raw fp32, flat [64][128] floats (8 cp / thread)
#pragma unroll
    for (int i = 0; i < 8; i++) {
        int f = tid + 256 * i;
        int r = f >> 5;
        int q = f & 31;
        const float* wp = w2 + ((size_t)e * H_DIM + k0 + r) * F_DIM + n0 + q * 4;
        CP16(db + G2_ST + f * 16, wp);
    }
}

// ---------------- in-kernel converters (read own staging; pre-sync legal) -----
__device__ __forceinline__ void g1_convert(char* stage, int tid) {
    const char* stg = stage + G1_ST;
#pragma unroll
    for (int i = 0; i < 8; i++) {
        int f = tid + 256 * i;
        int mat = f >> 10;
        int r = (f >> 5) & 31;
        int q = f & 31;
        float4 v = *reinterpret_cast<const float4*>(stg + f * 16);
        uint32_t h01, l01, h23, l23;
        split_pair(v.x, v.y, h01, l01);
        split_pair(v.z, v.w, h23, l23);
        uint32_t doff = r * SB_STRIDE + q * 8;
        char* hB = stage + (mat ? G1_B3H : G1_B1H);
        char* lB = stage + (mat ? G1_B3L : G1_B1L);
        *reinterpret_cast<uint2*>(hB + doff) = make_uint2(h01, h23);
        *reinterpret_cast<uint2*>(lB + doff) = make_uint2(l01, l23);
    }
}

__device__ __forceinline__ void g2_convert(char* stage, int tid) {
    const char* stg = stage + G2_ST;
#pragma unroll
    for (int i = 0; i < 8; i++) {
        int f = tid + 256 * i;
        int r = f >> 5;
        int q = f & 31;
        float4 v = *reinterpret_cast<const float4*>(stg + f * 16);
        uint32_t h01, l01, h23, l23;
        split_pair(v.x, v.y, h01, l01);
        split_pair(v.z, v.w, h23, l23);
        uint32_t doff = r * SB_STRIDE + q * 8;
        *reinterpret_cast<uint2*>(stage + G2_BH + doff) = make_uint2(h01, h23);
        *reinterpret_cast<uint2*>(stage + G2_BL + doff) = make_uint2(l01, l23);
    }
}

// ============================================================================
// GEMM1: D1 = Xg @ w1[:, n0:n0+128], D3 = Xg @ w3[...]; H = silu(D1)*D3
// ============================================================================
__global__ __launch_bounds__(256, 1)
void gemm1_mma(const float* __restrict__ w1, const float* __restrict__ w3) {
    const int e = blockIdx.z;
    const int cnt = g_count[e];
    const int m0 = blockIdx.y * 128;
    if (m0 >= cnt) return;
    const int n0 = blockIdx.x * 128;

    extern __shared__ char dsm[];
    const uint32_t sb = smem_u32(dsm);

    const int tid = threadIdx.x;
    const int wid = tid >> 5;
    const int lane = tid & 31;
    const int mw = wid & 1;     // 2 M-warps (64 rows each)
    const int nw = wid >> 1;    // 4 N-warps (32 cols each)

    const int rr0 = tid >> 2;
    const int rr1 = 64 + rr0;
    int tok0 = g_pair_token[e * SEG + m0 + rr0]; if (m0 + rr0 >= cnt) tok0 = 0;
    int tok1 = g_pair_token[e * SEG + m0 + rr1]; if (m0 + rr1 >= cnt) tok1 = 0;

    const int j  = lane >> 3;
    const int rA = lane & 7;
    const uint32_t aRow  = (mw * 64 + (j & 1) * 8 + rA) * SA1_STRIDE + ((j >> 1) * 8) * 2;
    const uint32_t bBase = ((j & 1) * 8 + rA) * SB_STRIDE + (nw * 32 + (j >> 1) * 8) * 2;

    float acc1[4][4][4], acc3[4][4][4];
#pragma unroll
    for (int mt = 0; mt < 4; mt++)
#pragma unroll
        for (int nt = 0; nt < 4; nt++)
#pragma unroll
            for (int k = 0; k < 4; k++) { acc1[mt][nt][k] = 0.f; acc3[mt][nt][k] = 0.f; }

    g1_load(sb, 0, tid, tok0, tok1, e, n0, w1, w3);
    CP_COMMIT();

    for (int c = 0; c < NC1; c++) {
        CP_WAIT0();
        g1_convert(dsm + (c & 1) * G1_STAGE, tid);   // own staging -> tiles (pre-sync)
        __syncthreads();                              // publish tiles; all past mma(c-1)
        if (c + 1 < NC1) {
            g1_load(sb + ((c + 1) & 1) * G1_STAGE, (c + 1) * 32, tid,
                    tok0, tok1, e, n0, w1, w3);
            CP_COMMIT();
        }

        const uint32_t tb = sb + (c & 1) * G1_STAGE;
#pragma unroll
        for (int kk = 0; kk < 32; kk += 16) {
            uint32_t aH[4][4], aL[4][4];
#pragma unroll
            for (int mt = 0; mt < 4; mt++) {
                ldsm_x4(tb + G1_AH + aRow + mt * (16 * SA1_STRIDE) + kk * 2, aH[mt]);
                ldsm_x4(tb + G1_AL + aRow + mt * (16 * SA1_STRIDE) + kk * 2, aL[mt]);
            }
            uint32_t bH[8], bL[8];
            // ---- w1 planes ----
            ldsm_x4_t(tb + G1_B1H + bBase + kk * SB_STRIDE,      bH);
            ldsm_x4_t(tb + G1_B1H + bBase + kk * SB_STRIDE + 32, bH + 4);
            ldsm_x4_t(tb + G1_B1L + bBase + kk * SB_STRIDE,      bL);
            ldsm_x4_t(tb + G1_B1L + bBase + kk * SB_STRIDE + 32, bL + 4);
#pragma unroll
            for (int mt = 0; mt < 4; mt++)
#pragma unroll
                for (int nt = 0; nt < 4; nt++) {
                    mma_bf16(acc1[mt][nt], aH[mt], bH + nt * 2);
                    mma_bf16(acc1[mt][nt], aL[mt], bH + nt * 2);
                    mma_bf16(acc1[mt][nt], aH[mt], bL + nt * 2);
                }
            // ---- w3 planes ----
            ldsm_x4_t(tb + G1_B3H + bBase + kk * SB_STRIDE,      bH);
            ldsm_x4_t(tb + G1_B3H + bBase + kk * SB_STRIDE + 32, bH + 4);
            ldsm_x4_t(tb + G1_B3L + bBase + kk * SB_STRIDE,      bL);
            ldsm_x4_t(tb + G1_B3L + bBase + kk * SB_STRIDE + 32, bL + 4);
#pragma unroll
            for (int mt = 0; mt < 4; mt++)
#pragma unroll
                for (int nt = 0; nt < 4; nt++) {
                    mma_bf16(acc3[mt][nt], aH[mt], bH + nt * 2);
                    mma_bf16(acc3[mt][nt], aL[mt], bH + nt * 2);
                    mma_bf16(acc3[mt][nt], aH[mt], bL + nt * 2);
                }
        }
    }

    // epilogue: silu(D1)*D3 -> bf16 hi/lo H
#pragma unroll
    for (int mt = 0; mt < 4; mt++) {
        const int rbase = mw * 64 + mt * 16 + (lane >> 2);
#pragma unroll
        for (int half = 0; half < 2; half++) {
            const int r = rbase + half * 8;
            if (m0 + r < cnt) {
                const size_t rowoff = (size_t)(e * SEG + m0 + r) * H_DIM;
#pragma unroll
                for (int nt = 0; nt < 4; nt++) {
                    const int colg = n0 + nw * 32 + nt * 8 + 2 * (lane & 3);
                    float a0 = acc1[mt][nt][half * 2 + 0];
                    float a1 = acc1[mt][nt][half * 2 + 1];
                    float g0 = acc3[mt][nt][half * 2 + 0];
                    float g1 = acc3[mt][nt][half * 2 + 1];
                    float y0 = a0 / (1.f + expf(-a0)) * g0;
                    float y1 = a1 / (1.f + expf(-a1)) * g1;
                    uint32_t hi, lo;
                    split_pair(y0, y1, hi, lo);
                    *reinterpret_cast<uint32_t*>(g_Hh + rowoff + colg) = hi;
                    *reinterpret_cast<uint32_t*>(g_Hl + rowoff + colg) = lo;
                }
            }
        }
    }
}

// ============================================================================
// GEMM2: out[tok] += w * (H @ w2[:, n0:n0+128]), K-chunk 64
// ============================================================================
__global__ __launch_bounds__(256, 1)
void gemm2_mma(const float* __restrict__ w2, float* __restrict__ out) {
    const int e = blockIdx.z;
    const int cnt = g_count[e];
    const int m0 = blockIdx.y * 128;
    if (m0 >= cnt) return;
    const int n0 = blockIdx.x * 128;

    extern __shared__ char dsm[];
    const uint32_t sb = smem_u32(dsm);

    const int tid = threadIdx.x;
    const int wid = tid >> 5;
    const int lane = tid & 31;
    const int mw = wid & 1;
    const int nw = wid >> 1;

    const int j  = lane >> 3;
    const int rA = lane & 7;
    const uint32_t aRow  = (mw * 64 + (j & 1) * 8 + rA) * SA2_STRIDE + ((j >> 1) * 8) * 2;
    const uint32_t bBase = ((j & 1) * 8 + rA) * SB_STRIDE + (nw * 32 + (j >> 1) * 8) * 2;

    float acc[4][4][4];
#pragma unroll
    for (int mt = 0; mt < 4; mt++)
#pragma unroll
        for (int nt = 0; nt < 4; nt++)
#pragma unroll
            for (int k = 0; k < 4; k++) acc[mt][nt][k] = 0.f;

    g2_load(sb, 0, tid, e, m0, n0, w2);
    CP_COMMIT();

    for (int c = 0; c < NC2; c++) {
        CP_WAIT0();
        g2_convert(dsm + (c & 1) * G2_STAGE, tid);
        __syncthreads();
        if (c + 1 < NC2) {
            g2_load(sb + ((c + 1) & 1) * G2_STAGE, (c + 1) * 64, tid, e, m0, n0, w2);
            CP_COMMIT();
        }

        const uint32_t tb = sb + (c & 1) * G2_STAGE;
#pragma unroll
        for (int kk = 0; kk < 64; kk += 16) {
            uint32_t aH[4][4], aL[4][4];
#pragma unroll
            for (int mt = 0; mt < 4; mt++) {
                ldsm_x4(tb + G2_AH + aRow + mt * (16 * SA2_STRIDE) + kk * 2, aH[mt]);
                ldsm_x4(tb + G2_AL + aRow + mt * (16 * SA2_STRIDE) + kk * 2, aL[mt]);
            }
            uint32_t bH[8], bL[8];
            ldsm_x4_t(tb + G2_BH + bBase + kk * SB_STRIDE,      bH);
            ldsm_x4_t(tb + G2_BH + bBase + kk * SB_STRIDE + 32, bH + 4);
            ldsm_x4_t(tb + G2_BL + bBase + kk * SB_STRIDE,      bL);
            ldsm_x4_t(tb + G2_BL + bBase + kk * SB_STRIDE + 32, bL + 4);
#pragma unroll
            for (int mt = 0; mt < 4; mt++)
#pragma unroll
                for (int nt = 0; nt < 4; nt++) {
                    mma_bf16(acc[mt][nt], aH[mt], bH + nt * 2);
                    mma_bf16(acc[mt][nt], aL[mt], bH + nt * 2);
                    mma_bf16(acc[mt][nt], aH[mt], bL + nt * 2);
                }
        }
    }

    // epilogue: weighted atomic scatter
#pragma unroll
    for (int mt = 0; mt < 4; mt++) {
        const int rbase = mw * 64 + mt * 16 + (lane >> 2);
#pragma unroll
        for (int half = 0; half < 2; half++) {
            const int r = rbase + half * 8;
            if (m0 + r < cnt) {
                const int tok = g_pair_token[e * SEG + m0 + r];
                const float wgt = g_pair_w[e * SEG + m0 + r];
                float* ob = out + (size_t)tok * F_DIM;
#pragma unroll
                for (int nt = 0; nt < 4; nt++) {
                    const int colg = n0 + nw * 32 + nt * 8 + 2 * (lane & 3);
                    atomicAdd(ob + colg,     wgt * acc[mt][nt][half * 2 + 0]);
                    atomicAdd(ob + colg + 1, wgt * acc[mt][nt][half * 2 + 1]);
                }
            }
        }
    }
}

// ---------------- launch ------------------------------------------------------
extern "C" void kernel_launch(void* const* d_in, const int* in_sizes, int n_in,
                              void* d_out, int out_size) {
    const float* x  = (const float*)d_in[0];
    const float* gw = (const float*)d_in[1];
    const float* w1 = (const float*)d_in[2];
    const float* w2 = (const float*)d_in[3];
    const float* w3 = (const float*)d_in[4];
    float* out = (float*)d_out;

    cudaFuncSetAttribute(gemm1_mma, cudaFuncAttributeMaxDynamicSharedMemorySize, G1_SMEM);
    cudaFuncSetAttribute(gemm2_mma, cudaFuncAttributeMaxDynamicSharedMemorySize, G2_SMEM);

    zero_out_kernel<<<512, 256>>>(out);
    router_kernel<<<N_TOKENS, 128>>>(x, gw);
    compact_kernel<<<N_EXP, 256>>>();
    gemm1_mma<<<dim3(H_DIM / 128, SEG / 128, N_EXP), 256, G1_SMEM>>>(w1, w3);
    gemm2_mma<<<dim3(F_DIM / 128, SEG / 128, N_EXP), 256, G2_SMEM>>>(w2, out);
}

// round 15
// speedup vs baseline: 1.1695x; 1.0363x over previous
#include <cuda_runtime.h>
#include <cuda_bf16.h>
#include <cstdint>
#include <math.h>

// Problem constants
#define N_TOKENS 2048
#define F_DIM    2048
#define H_DIM    4096
#define N_EXP    8
#define SEG      2048

// ---------------- device scratch (static globals) ---------------------------
__device__ int   g_topk_idx[N_TOKENS * 2];
__device__ float g_topk_w[N_TOKENS * 2];
__device__ int   g_pair_token[N_EXP * SEG];
__device__ float g_pair_w[N_EXP * SEG];
__device__ int   g_count[N_EXP];

// bf16 hi/lo planes for x and H (weights converted in-kernel)
__device__ __align__(16) __nv_bfloat16 g_Xh[(size_t)N_TOKENS * F_DIM];
__device__ __align__(16) __nv_bfloat16 g_Xl[(size_t)N_TOKENS * F_DIM];
__device__ __align__(16) __nv_bfloat16 g_Hh[(size_t)N_EXP * SEG * H_DIM];
__device__ __align__(16) __nv_bfloat16 g_Hl[(size_t)N_EXP * SEG * H_DIM];

// ---------------- PTX helpers ------------------------------------------------
__device__ __forceinline__ uint32_t smem_u32(const void* p) {
    uint32_t a;
    asm("{ .reg .u64 t; cvta.to.shared.u64 t, %1; cvt.u32.u64 %0, t; }" : "=r"(a) : "l"(p));
    return a;
}

#define CP16(dst, src) \
    asm volatile("cp.async.cg.shared.global [%0], [%1], 16;" \
                 :: "r"(dst), "l"(src) : "memory")
#define CP_COMMIT() asm volatile("cp.async.commit_group;" ::: "memory")
#define CP_WAIT0()  asm volatile("cp.async.wait_group 0;" ::: "memory")

__device__ __forceinline__ void ldsm_x4(uint32_t addr, uint32_t* r) {
    asm volatile("ldmatrix.sync.aligned.m8n8.x4.shared.b16 {%0,%1,%2,%3}, [%4];"
                 : "=r"(r[0]), "=r"(r[1]), "=r"(r[2]), "=r"(r[3]) : "r"(addr));
}
__device__ __forceinline__ void ldsm_x4_t(uint32_t addr, uint32_t* r) {
    asm volatile("ldmatrix.sync.aligned.m8n8.x4.trans.shared.b16 {%0,%1,%2,%3}, [%4];"
                 : "=r"(r[0]), "=r"(r[1]), "=r"(r[2]), "=r"(r[3]) : "r"(addr));
}
__device__ __forceinline__ void mma_bf16(float* d, const uint32_t* a, const uint32_t* b) {
    asm volatile(
        "mma.sync.aligned.m16n8k16.row.col.f32.bf16.bf16.f32 "
        "{%0,%1,%2,%3}, {%4,%5,%6,%7}, {%8,%9}, {%0,%1,%2,%3};"
        : "+f"(d[0]), "+f"(d[1]), "+f"(d[2]), "+f"(d[3])
        : "r"(a[0]), "r"(a[1]), "r"(a[2]), "r"(a[3]), "r"(b[0]), "r"(b[1]));
}

__device__ __forceinline__ void split_pair(float y0, float y1, uint32_t& hi, uint32_t& lo) {
    uint32_t u0 = __float_as_uint(y0), u1 = __float_as_uint(y1);
    hi = __byte_perm(u0, u1, 0x7632);
    float l0 = y0 - __uint_as_float(u0 & 0xffff0000u);
    float l1 = y1 - __uint_as_float(u1 & 0xffff0000u);
    lo = __byte_perm(__float_as_uint(l0), __float_as_uint(l1), 0x7632);
}

// ---------------- router (zeros out rows, emits Xh/Xl split, routes) ---------
__global__ void router_kernel(const float* __restrict__ x,
                              const float* __restrict__ gw,
                              float* __restrict__ out) {
    const int t = blockIdx.x;
    const float* xr = x + (size_t)t * F_DIM;
    uint16_t* xh = reinterpret_cast<uint16_t*>(g_Xh) + (size_t)t * F_DIM;
    uint16_t* xl = reinterpret_cast<uint16_t*>(g_Xl) + (size_t)t * F_DIM;

    // zero this token's output row (replaces zero_out_kernel)
    float4* orow = reinterpret_cast<float4*>(out + (size_t)t * F_DIM);
    float4 z = make_float4(0.f, 0.f, 0.f, 0.f);
#pragma unroll
    for (int i = 0; i < F_DIM / 4 / 128; i++)
        orow[threadIdx.x + 128 * i] = z;

    float p[N_EXP];
#pragma unroll
    for (int e = 0; e < N_EXP; e++) p[e] = 0.f;
    for (int i = threadIdx.x; i < F_DIM; i += blockDim.x) {
        float xv = xr[i];
        uint32_t u = __float_as_uint(xv);
        xh[i] = (uint16_t)(u >> 16);
        float lo = xv - __uint_as_float(u & 0xffff0000u);
        xl[i] = (uint16_t)(__float_as_uint(lo) >> 16);
#pragma unroll
        for (int e = 0; e < N_EXP; e++) p[e] += xv * gw[e * F_DIM + i];
    }
    __shared__ float red[N_EXP][128];
#pragma unroll
    for (int e = 0; e < N_EXP; e++) red[e][threadIdx.x] = p[e];
    __syncthreads();
    for (int s = 64; s > 0; s >>= 1) {
        if (threadIdx.x < s) {
#pragma unroll
            for (int e = 0; e < N_EXP; e++)
                red[e][threadIdx.x] += red[e][threadIdx.x + s];
        }
        __syncthreads();
    }
    if (threadIdx.x == 0) {
        float l[N_EXP];
#pragma unroll
        for (int e = 0; e < N_EXP; e++) l[e] = red[e][0];
        int e1 = 0;
#pragma unroll
        for (int e = 1; e < N_EXP; e++) if (l[e] > l[e1]) e1 = e;
        int e2 = (e1 == 0) ? 1 : 0;
#pragma unroll
        for (int e = 0; e < N_EXP; e++)
            if (e != e1 && l[e] > l[e2]) e2 = e;
        float d  = l[e2] - l[e1];
        float eb = expf(d);
        g_topk_idx[2 * t + 0] = e1;
        g_topk_idx[2 * t + 1] = e2;
        g_topk_w[2 * t + 0] = 1.f / (1.f + eb);
        g_topk_w[2 * t + 1] = eb / (1.f + eb);
    }
}

// ---------------- deterministic compaction -----------------------------------
__global__ void compact_kernel() {
    const int e = blockIdx.x;
    const int t = threadIdx.x;
    const int T0 = t * (N_TOKENS / 256);
    int flags[N_TOKENS / 256];
    int c = 0;
#pragma unroll
    for (int i = 0; i < N_TOKENS / 256; i++) {
        int tok = T0 + i;
        int f = -1;
        if (g_topk_idx[2 * tok + 0] == e) f = 0;
        else if (g_topk_idx[2 * tok + 1] == e) f = 1;
        flags[i] = f;
        if (f >= 0) c++;
    }
    __shared__ int s[256];
    s[t] = c;
    __syncthreads();
    for (int off = 1; off < 256; off <<= 1) {
        int v = (t >= off) ? s[t - off] : 0;
        __syncthreads();
        s[t] += v;
        __syncthreads();
    }
    int pos = e * SEG + (s[t] - c);
#pragma unroll
    for (int i = 0; i < N_TOKENS / 256; i++) {
        int f = flags[i];
        if (f >= 0) {
            int tok = T0 + i;
            g_pair_token[pos] = tok;
            g_pair_w[pos] = g_topk_w[2 * tok + f];
            pos++;
        }
    }
    if (t == 255) g_count[e] = s[255];
}

// ============================================================================
// GEMM1 geometry: block M=128, N=128, K-chunk 32; 8 warps as 2M x 4N
// GEMM2 geometry: K-chunk 64
// ============================================================================
#define SA1_STRIDE 80
#define SA2_STRIDE 144
#define SB_STRIDE  272

#define G1_AH    0
#define G1_AL    10240
#define G1_B1H   20480
#define G1_B1L   29184
#define G1_B3H   37888
#define G1_B3L   46592
#define G1_ST    55296
#define G1_STAGE 88064
#define G1_SMEM  (2 * G1_STAGE)
#define NC1 (F_DIM / 32)

#define G2_AH    0
#define G2_AL    18432
#define G2_BH    36864
#define G2_BL    54272
#define G2_ST    71680
#define G2_STAGE 104448
#define G2_SMEM  (2 * G2_STAGE)
#define NC2 (H_DIM / 64)

// ---------------- stage loaders -----------------------------------------------
__device__ __forceinline__ void g1_load(uint32_t db, int k0, int tid,
                                        int tok0, int tok1, int e, int n0,
                                        const float* __restrict__ w1,
                                        const float* __restrict__ w3) {
#pragma unroll
    for (int i = 0; i < 4; i++) {
        int p  = i >> 1;
        int rr = ((i & 1) << 6) + (tid >> 2);
        int q  = tid & 3;
        int tk = (i & 1) ? tok1 : tok0;
        const __nv_bfloat16* sp = (p ? g_Xl : g_Xh) + (size_t)tk * F_DIM + k0 + q * 8;
        CP16(db + (p ? G1_AL : G1_AH) + rr * SA1_STRIDE + q * 16, sp);
    }
#pragma unroll
    for (int i = 0; i < 8; i++) {
        int f = tid + 256 * i;
        int mat = f >> 10;
        int rem = f & 1023;
        int r = rem >> 5;
        int q = rem & 31;
        const float* wp = (mat ? w3 : w1)
            + ((size_t)e * F_DIM + k0 + r) * H_DIM + n0 + q * 4;
        CP16(db + G1_ST + f * 16, wp);
    }
}

__device__ __forceinline__ void g2_load(uint32_t db, int k0, int tid,
                                        int e, int m0, int n0,
                                        const float* __restrict__ w2) {
#pragma unroll
    for (int i = 0; i < 8; i++) {
        int p  = i >> 2;
        int f  = tid + 256 * (i & 3);
        int rr = f >> 3;
        int q  = f & 7;
        const __nv_bfloat16* sp = (p ? g_Hl : g_Hh)
            + (size_t)(e * SEG + m0 + rr) * H_DIM + k0 + q * 8;
        CP16(db + (p ? G2_AL : G2_AH) + rr * SA2_STRIDE + q * 16, sp);
    }
#pragma unroll
    for (int i = 0; i < 8; i++) {
        int f = tid + 256 * i;
        int r = f >> 5;
        int q = f & 31;
        const float* wp = w2 + ((size_t)e * H_DIM + k0 + r) * F_DIM + n0 + q * 4;
        CP16(db + G2_ST + f * 16, wp);
    }
}

// ---------------- in-kernel converters (read own staging slots only) ----------
__device__ __forceinline__ void g1_convert(char* stage, int tid) {
    const char* stg = stage + G1_ST;
#pragma unroll
    for (int i = 0; i < 8; i++) {
        int f = tid + 256 * i;
        int mat = f >> 10;
        int r = (f >> 5) & 31;
        int q = f & 31;
        float4 v = *reinterpret_cast<const float4*>(stg + f * 16);
        uint32_t h01, l01, h23, l23;
        split_pair(v.x, v.y, h01, l01);
        split_pair(v.z, v.w, h23, l23);
        uint32_t doff = r * SB_STRIDE + q * 8;
        char* hB = stage + (mat ? G1_B3H : G1_B1H);
        char* lB = stage + (mat ? G1_B3L : G1_B1L);
        *reinterpret_cast<uint2*>(hB + doff) = make_uint2(h01, h23);
        *reinterpret_cast<uint2*>(lB + doff) = make_uint2(l01, l23);
    }
}

__device__ __forceinline__ void g2_convert(char* stage, int tid) {
    const char* stg = stage + G2_ST;
#pragma unroll
    for (int i = 0; i < 8; i++) {
        int f = tid + 256 * i;
        int r = f >> 5;
        int q = f & 31;
        float4 v = *reinterpret_cast<const float4*>(stg + f * 16);
        uint32_t h01, l01, h23, l23;
        split_pair(v.x, v.y, h01, l01);
        split_pair(v.z, v.w, h23, l23);
        uint32_t doff = r * SB_STRIDE + q * 8;
        *reinterpret_cast<uint2*>(stage + G2_BH + doff) = make_uint2(h01, h23);
        *reinterpret_cast<uint2*>(stage + G2_BL + doff) = make_uint2(l01, l23);
    }
}

// ============================================================================
// GEMM1: D1 = Xg @ w1[:, n0:n0+128], D3 = Xg @ w3[...]; H = silu(D1)*D3
// Overlapped pipeline: convert(c+1) interleaved inside mma(c)
// ============================================================================
__global__ __launch_bounds__(256, 1)
void gemm1_mma(const float* __restrict__ w1, const float* __restrict__ w3) {
    const int e = blockIdx.z;
    const int cnt = g_count[e];
    const int m0 = blockIdx.y * 128;
    if (m0 >= cnt) return;
    const int n0 = blockIdx.x * 128;

    extern __shared__ char dsm[];
    const uint32_t sb = smem_u32(dsm);

    const int tid = threadIdx.x;
    const int wid = tid >> 5;
    const int lane = tid & 31;
    const int mw = wid & 1;
    const int nw = wid >> 1;

    const int rr0 = tid >> 2;
    const int rr1 = 64 + rr0;
    int tok0 = g_pair_token[e * SEG + m0 + rr0]; if (m0 + rr0 >= cnt) tok0 = 0;
    int tok1 = g_pair_token[e * SEG + m0 + rr1]; if (m0 + rr1 >= cnt) tok1 = 0;

    const int j  = lane >> 3;
    const int rA = lane & 7;
    const uint32_t aRow  = (mw * 64 + (j & 1) * 8 + rA) * SA1_STRIDE + ((j >> 1) * 8) * 2;
    const uint32_t bBase = ((j & 1) * 8 + rA) * SB_STRIDE + (nw * 32 + (j >> 1) * 8) * 2;

    float acc1[4][4][4], acc3[4][4][4];
#pragma unroll
    for (int mt = 0; mt < 4; mt++)
#pragma unroll
        for (int nt = 0; nt < 4; nt++)
#pragma unroll
            for (int k = 0; k < 4; k++) { acc1[mt][nt][k] = 0.f; acc3[mt][nt][k] = 0.f; }

    // prologue: chunk 0 staged + converted
    g1_load(sb, 0, tid, tok0, tok1, e, n0, w1, w3);
    CP_COMMIT();
    CP_WAIT0();
    g1_convert(dsm, tid);
    __syncthreads();

    for (int c = 0; c < NC1; c++) {
        const uint32_t tb = sb + (c & 1) * G1_STAGE;
        const bool more = (c + 1 < NC1);
        if (more) {
            g1_load(sb + ((c + 1) & 1) * G1_STAGE, (c + 1) * 32, tid,
                    tok0, tok1, e, n0, w1, w3);
            CP_COMMIT();
        }

#pragma unroll
        for (int kk = 0; kk < 32; kk += 16) {
            uint32_t aH[4][4], aL[4][4];
#pragma unroll
            for (int mt = 0; mt < 4; mt++) {
                ldsm_x4(tb + G1_AH + aRow + mt * (16 * SA1_STRIDE) + kk * 2, aH[mt]);
                ldsm_x4(tb + G1_AL + aRow + mt * (16 * SA1_STRIDE) + kk * 2, aL[mt]);
            }
            uint32_t bH[8], bL[8];
            // ---- w1 planes (term-major: independent HMMAs between acc reuses)
            ldsm_x4_t(tb + G1_B1H + bBase + kk * SB_STRIDE,      bH);
            ldsm_x4_t(tb + G1_B1H + bBase + kk * SB_STRIDE + 32, bH + 4);
            ldsm_x4_t(tb + G1_B1L + bBase + kk * SB_STRIDE,      bL);
            ldsm_x4_t(tb + G1_B1L + bBase + kk * SB_STRIDE + 32, bL + 4);
#pragma unroll
            for (int mt = 0; mt < 4; mt++)
#pragma unroll
                for (int nt = 0; nt < 4; nt++)
                    mma_bf16(acc1[mt][nt], aH[mt], bH + nt * 2);
#pragma unroll
            for (int mt = 0; mt < 4; mt++)
#pragma unroll
                for (int nt = 0; nt < 4; nt++)
                    mma_bf16(acc1[mt][nt], aL[mt], bH + nt * 2);
#pragma unroll
            for (int mt = 0; mt < 4; mt++)
#pragma unroll
                for (int nt = 0; nt < 4; nt++)
                    mma_bf16(acc1[mt][nt], aH[mt], bL + nt * 2);
            // ---- w3 planes
            ldsm_x4_t(tb + G1_B3H + bBase + kk * SB_STRIDE,      bH);
            ldsm_x4_t(tb + G1_B3H + bBase + kk * SB_STRIDE + 32, bH + 4);
            ldsm_x4_t(tb + G1_B3L + bBase + kk * SB_STRIDE,      bL);
            ldsm_x4_t(tb + G1_B3L + bBase + kk * SB_STRIDE + 32, bL + 4);
#pragma unroll
            for (int mt = 0; mt < 4; mt++)
#pragma unroll
                for (int nt = 0; nt < 4; nt++)
                    mma_bf16(acc3[mt][nt], aH[mt], bH + nt * 2);
#pragma unroll
            for (int mt = 0; mt < 4; mt++)
#pragma unroll
                for (int nt = 0; nt < 4; nt++)
                    mma_bf16(acc3[mt][nt], aL[mt], bH + nt * 2);
#pragma unroll
            for (int mt = 0; mt < 4; mt++)
#pragma unroll
                for (int nt = 0; nt < 4; nt++)
                    mma_bf16(acc3[mt][nt], aH[mt], bL + nt * 2);

            // interleave next chunk's convert between the two kk halves
            if (kk == 0 && more) {
                CP_WAIT0();  // staging(c+1) arrived (A tiles too)
                g1_convert(dsm + ((c + 1) & 1) * G1_STAGE, tid);
            }
        }
        __syncthreads();   // publish tiles(c+1); everyone past mma(c)
    }

    // epilogue: silu(D1)*D3 -> bf16 hi/lo H
#pragma unroll
    for (int mt = 0; mt < 4; mt++) {
        const int rbase = mw * 64 + mt * 16 + (lane >> 2);
#pragma unroll
        for (int half = 0; half < 2; half++) {
            const int r = rbase + half * 8;
            if (m0 + r < cnt) {
                const size_t rowoff = (size_t)(e * SEG + m0 + r) * H_DIM;
#pragma unroll
                for (int nt = 0; nt < 4; nt++) {
                    const int colg = n0 + nw * 32 + nt * 8 + 2 * (lane & 3);
                    float a0 = acc1[mt][nt][half * 2 + 0];
                    float a1 = acc1[mt][nt][half * 2 + 1];
                    float g0 = acc3[mt][nt][half * 2 + 0];
                    float g1 = acc3[mt][nt][half * 2 + 1];
                    float y0 = a0 / (1.f + expf(-a0)) * g0;
                    float y1 = a1 / (1.f + expf(-a1)) * g1;
                    uint32_t hi, lo;
                    split_pair(y0, y1, hi, lo);
                    *reinterpret_cast<uint32_t*>(g_Hh + rowoff + colg) = hi;
                    *reinterpret_cast<uint32_t*>(g_Hl + rowoff + colg) = lo;
                }
            }
        }
    }
}

// ============================================================================
// GEMM2: out[tok] += w * (H @ w2[:, n0:n0+128]), K-chunk 64, overlapped convert
// ============================================================================
__global__ __launch_bounds__(256, 1)
void gemm2_mma(const float* __restrict__ w2, float* __restrict__ out) {
    const int e = blockIdx.z;
    const int cnt = g_count[e];
    const int m0 = blockIdx.y * 128;
    if (m0 >= cnt) return;
    const int n0 = blockIdx.x * 128;

    extern __shared__ char dsm[];
    const uint32_t sb = smem_u32(dsm);

    const int tid = threadIdx.x;
    const int wid = tid >> 5;
    const int lane = tid & 31;
    const int mw = wid & 1;
    const int nw = wid >> 1;

    const int j  = lane >> 3;
    const int rA = lane & 7;
    const uint32_t aRow  = (mw * 64 + (j & 1) * 8 + rA) * SA2_STRIDE + ((j >> 1) * 8) * 2;
    const uint32_t bBase = ((j & 1) * 8 + rA) * SB_STRIDE + (nw * 32 + (j >> 1) * 8) * 2;

    float acc[4][4][4];
#pragma unroll
    for (int mt = 0; mt < 4; mt++)
#pragma unroll
        for (int nt = 0; nt < 4; nt++)
#pragma unroll
            for (int k = 0; k < 4; k++) acc[mt][nt][k] = 0.f;

    g2_load(sb, 0, tid, e, m0, n0, w2);
    CP_COMMIT();
    CP_WAIT0();
    g2_convert(dsm, tid);
    __syncthreads();

    for (int c = 0; c < NC2; c++) {
        const uint32_t tb = sb + (c & 1) * G2_STAGE;
        const bool more = (c + 1 < NC2);
        if (more) {
            g2_load(sb + ((c + 1) & 1) * G2_STAGE, (c + 1) * 64, tid, e, m0, n0, w2);
            CP_COMMIT();
        }

#pragma unroll
        for (int kk = 0; kk < 64; kk += 16) {
            uint32_t aH[4][4], aL[4][4];
#pragma unroll
            for (int mt = 0; mt < 4; mt++) {
                ldsm_x4(tb + G2_AH + aRow + mt * (16 * SA2_STRIDE) + kk * 2, aH[mt]);
                ldsm_x4(tb + G2_AL + aRow + mt * (16 * SA2_STRIDE) + kk * 2, aL[mt]);
            }
            uint32_t bH[8], bL[8];
            ldsm_x4_t(tb + G2_BH + bBase + kk * SB_STRIDE,      bH);
            ldsm_x4_t(tb + G2_BH + bBase + kk * SB_STRIDE + 32, bH + 4);
            ldsm_x4_t(tb + G2_BL + bBase + kk * SB_STRIDE,      bL);
            ldsm_x4_t(tb + G2_BL + bBase + kk * SB_STRIDE + 32, bL + 4);
#pragma unroll
            for (int mt = 0; mt < 4; mt++)
#pragma unroll
                for (int nt = 0; nt < 4; nt++)
                    mma_bf16(acc[mt][nt], aH[mt], bH + nt * 2);
#pragma unroll
            for (int mt = 0; mt < 4; mt++)
#pragma unroll
                for (int nt = 0; nt < 4; nt++)
                    mma_bf16(acc[mt][nt], aL[mt], bH + nt * 2);
#pragma unroll
            for (int mt = 0; mt < 4; mt++)
#pragma unroll
                for (int nt = 0; nt < 4; nt++)
                    mma_bf16(acc[mt][nt], aH[mt], bL + nt * 2);

            if (kk == 16 && more) {
                CP_WAIT0();
                g2_convert(dsm + ((c + 1) & 1) * G2_STAGE, tid);
            }
        }
        __syncthreads();
    }

    // epilogue: weighted atomic scatter
#pragma unroll
    for (int mt = 0; mt < 4; mt++) {
        const int rbase = mw * 64 + mt * 16 + (lane >> 2);
#pragma unroll
        for (int half = 0; half < 2; half++) {
            const int r = rbase + half * 8;
            if (m0 + r < cnt) {
                const int tok = g_pair_token[e * SEG + m0 + r];
                const float wgt = g_pair_w[e * SEG + m0 + r];
                float* ob = out + (size_t)tok * F_DIM;
#pragma unroll
                for (int nt = 0; nt < 4; nt++) {
                    const int colg = n0 + nw * 32 + nt * 8 + 2 * (lane & 3);
                    atomicAdd(ob + colg,     wgt * acc[mt][nt][half * 2 + 0]);
                    atomicAdd(ob + colg + 1, wgt * acc[mt][nt][half * 2 + 1]);
                }
            }
        }
    }
}

// ---------------- launch ------------------------------------------------------
extern "C" void kernel_launch(void* const* d_in, const int* in_sizes, int n_in,
                              void* d_out, int out_size) {
    const float* x  = (const float*)d_in[0];
    const float* gw = (const float*)d_in[1];
    const float* w1 = (const float*)d_in[2];
    const float* w2 = (const float*)d_in[3];
    const float* w3 = (const float*)d_in[4];
    float* out = (float*)d_out;

    cudaFuncSetAttribute(gemm1_mma, cudaFuncAttributeMaxDynamicSharedMemorySize, G1_SMEM);
    cudaFuncSetAttribute(gemm2_mma, cudaFuncAttributeMaxDynamicSharedMemorySize, G2_SMEM);

    router_kernel<<<N_TOKENS, 128>>>(x, gw, out);
    compact_kernel<<<N_EXP, 256>>>();
    gemm1_mma<<<dim3(H_DIM / 128, SEG / 128, N_EXP), 256, G1_SMEM>>>(w1, w3);
    gemm2_mma<<<dim3(F_DIM / 128, SEG / 128, N_EXP), 256, G2_SMEM>>>(w2, out);
}